// round 6
// baseline (speedup 1.0000x reference)
#include <cuda_runtime.h>
#include <math_constants.h>
#include <stdint.h>

#define NTOT     18432
#define TPB      128
#define TILE     128
#define NSTRIP   48
#define NDIAG    48
#define NOFF     1128                /* C(48,2) */
#define NUNITS   1176
#define GRID     1179                /* 2 quantile + 1 std + 1176 pairwise */
#define NWARPS   4
#define GMAX     1024
#define SELMAX   48
#define SMEM_BYTES 4096              /* tile 128*16=2048 | gather 1024 f32 */
#define V4PT     36                  /* NTOT/4/TPB */

static const double NPAIRS_D = 18871296.0;
static const double RAND_STD = 1.75;
static const double IQR_RAND = 2.45;

__device__ double   g_pair_partial[NUNITS];
__device__ double   g_sum_d, g_sumsq_d;
__device__ float    g_qv[4];
__device__ unsigned g_done = 0;

__device__ __forceinline__ float sqrt_approx(float x) {
    float r; asm("sqrt.approx.f32 %0, %1;" : "=f"(r) : "f"(x)); return r;
}
__device__ __forceinline__ unsigned fkey(float f) {
    unsigned u = __float_as_uint(f);
    return (u & 0x80000000u) ? ~u : (u | 0x80000000u);
}
__device__ __forceinline__ float funkey(unsigned u) {
    unsigned bits = (u & 0x80000000u) ? (u & 0x7fffffffu) : ~u;
    return __uint_as_float(bits);
}
/* min(d,0.8)/0.8 = sqrt(sat(sq/0.64)) */
__device__ __forceinline__ float term_n(float sq) {
    return sqrt_approx(__saturatef(sq * 1.5625f));
}

__global__ void __launch_bounds__(TPB, 8)
dp_fused_kernel(const float* __restrict__ g, float* __restrict__ out) {
    extern __shared__ unsigned char smem_raw[];
    const int bid = blockIdx.x;
    const int t   = threadIdx.x;
    const int w   = t >> 5;
    const int ln  = t & 31;

    __shared__ unsigned s_wcnt[NWARPS];
    __shared__ unsigned s_tot, s_gcnt;
    __shared__ float    s_fred[NWARPS];
    __shared__ int      s_last;

    if (bid >= 3) {
        /* ================= pairwise unit ================= */
        const int pid = bid - 3;
        int a, b;
        if (pid < NDIAG) { a = b = pid; }
        else {
            int o = pid - NDIAG;
            a = 0; int rem = o;
            while (rem >= NSTRIP - 1 - a) { rem -= NSTRIP - 1 - a; ++a; }
            b = a + 1 + rem;
        }

        float4* tj = (float4*)smem_raw;
        {
            const int j = b * TILE + t;
            float xj = g[3 * j + 0], yj = g[3 * j + 1], zj = g[3 * j + 2];
            tj[t] = make_float4(xj, yj, zj,
                                fmaf(zj, zj, fmaf(yj, yj, xj * xj)));
        }
        __syncthreads();

        float xi, yi, zi;
        if (a == b) {
            float4 me = tj[t];
            xi = me.x; yi = me.y; zi = me.z;
        } else {
            const int i = a * TILE + t;
            xi = g[3 * i + 0]; yi = g[3 * i + 1]; zi = g[3 * i + 2];
        }
        const float ri = fmaf(zi, zi, fmaf(yi, yi, xi * xi));
        const float xm = -2.0f * xi, ym = -2.0f * yi, zm = -2.0f * zi;

        float acc0 = 0.f, acc1 = 0.f;

        if (a == b) {
            /* diag: wrap mapping, d = 1..63 all threads, d = 64 for t < 64 */
            #pragma unroll 7
            for (int d = 1; d <= 63; ++d) {
                float4 o = tj[(t + d) & (TILE - 1)];
                float s = ri + o.w;
                s = fmaf(o.x, xm, s);
                s = fmaf(o.y, ym, s);
                s = fmaf(o.z, zm, s);
                if (d & 1) acc0 += term_n(s); else acc1 += term_n(s);
            }
            if (t < TILE / 2) {
                float4 o = tj[(t + 64) & (TILE - 1)];
                float s = ri + o.w;
                s = fmaf(o.x, xm, s);
                s = fmaf(o.y, ym, s);
                s = fmaf(o.z, zm, s);
                acc0 += term_n(s);
            }
        } else {
            #pragma unroll 8
            for (int jj = 0; jj < TILE; jj += 2) {
                {
                    float4 o = tj[jj];
                    float s = ri + o.w;
                    s = fmaf(o.x, xm, s);
                    s = fmaf(o.y, ym, s);
                    s = fmaf(o.z, zm, s);
                    acc0 += term_n(s);
                }
                {
                    float4 o = tj[jj + 1];
                    float s = ri + o.w;
                    s = fmaf(o.x, xm, s);
                    s = fmaf(o.y, ym, s);
                    s = fmaf(o.z, zm, s);
                    acc1 += term_n(s);
                }
            }
        }

        float tot = acc0 + acc1;
        #pragma unroll
        for (int o = 16; o; o >>= 1)
            tot += __shfl_down_sync(0xffffffffu, tot, o);
        if (ln == 0) s_fred[w] = tot;
        __syncthreads();
        if (t == 0) {
            float r = (s_fred[0] + s_fred[1]) + (s_fred[2] + s_fred[3]);
            g_pair_partial[pid] = (double)r;
        }

    } else if (bid < 2) {
        /* ========= exact quantile pair (ranks k0, k0+1), 3-phase ========= */
        const int qb = bid;
        const unsigned k0 = qb ? 13823u : 4607u;
        const float gA = qb ? 0.6245f : -0.7245f;
        const float gB = qb ? 0.7245f : -0.6245f;
        const float4* gv4 = (const float4*)g;

        float lo = -CUDART_INF_F, hi = CUDART_INF_F;
        unsigned cL = 0, cH = NTOT;
        bool allEq = false;

        /* ---- phase 1: gmem passes (L1-resident) until bracket <= GMAX ---- */
        for (int it = 0; it < 48; ++it) {
            if (cH - cL <= (unsigned)GMAX) break;
            const unsigned klo = fkey(lo), khi = fkey(hi);
            if (khi - klo <= 1u) { allEq = true; break; }
            float cand;
            if (it == 0)      cand = gA;
            else if (it == 1) cand = gB;
            else if (it < 8) {
                double frac = ((double)k0 + 0.5 - (double)cL) / (double)(cH - cL);
                cand = (float)((double)lo + frac * ((double)hi - (double)lo));
            } else cand = funkey(klo + (khi - klo) / 2u);
            {
                unsigned kc = fkey(cand);
                if (!(kc > klo && kc < khi)) cand = funkey(klo + (khi - klo) / 2u);
            }
            unsigned c = 0;
            #pragma unroll 4
            for (int e = 0; e < V4PT; ++e) {
                float4 q = gv4[t + e * TPB];
                c += (q.x < cand) ? 1u : 0u;
                c += (q.y < cand) ? 1u : 0u;
                c += (q.z < cand) ? 1u : 0u;
                c += (q.w < cand) ? 1u : 0u;
            }
            #pragma unroll
            for (int o = 16; o; o >>= 1) c += __shfl_down_sync(0xffffffffu, c, o);
            if (ln == 0) s_wcnt[w] = c;
            __syncthreads();
            if (t == 0)
                s_tot = (s_wcnt[0] + s_wcnt[1]) + (s_wcnt[2] + s_wcnt[3]);
            __syncthreads();
            const unsigned ctot = s_tot;
            if (ctot <= k0) { lo = cand; cL = ctot; }
            else            { hi = cand; cH = ctot; }
        }

        if (allEq) {
            if (t == 0) { g_qv[2 * qb + 0] = lo; g_qv[2 * qb + 1] = lo; }
        } else {
            /* ---- gather bracket [lo,hi) into smem ---- */
            float* sub = (float*)smem_raw;
            if (t == 0) s_gcnt = 0;
            __syncthreads();
            #pragma unroll 4
            for (int e = 0; e < V4PT; ++e) {
                float4 q = gv4[t + e * TPB];
                float qq[4] = {q.x, q.y, q.z, q.w};
                #pragma unroll
                for (int c4 = 0; c4 < 4; ++c4) {
                    float x = qq[c4];
                    if (x >= lo && x < hi) {
                        unsigned p = atomicAdd(&s_gcnt, 1u);
                        if (p < (unsigned)GMAX) sub[p] = x;
                    }
                }
            }
            __syncthreads();
            const unsigned mm0 = s_gcnt;
            const unsigned cL0 = cL;

            /* ---- phase 2: smem count passes until bracket <= SELMAX ---- */
            unsigned cLg = cL, cHg = cH;
            float lo2 = lo, hi2 = hi;
            for (int it = 0; it < 64; ++it) {
                if (cHg - cLg <= (unsigned)SELMAX) break;
                const unsigned klo = fkey(lo2), khi = fkey(hi2);
                if (khi - klo <= 1u) break;
                float cand;
                if (it < 10) {
                    double frac = ((double)k0 + 0.5 - (double)cLg) / (double)(cHg - cLg);
                    cand = (float)((double)lo2 + frac * ((double)hi2 - (double)lo2));
                } else cand = funkey(klo + (khi - klo) / 2u);
                {
                    unsigned kc = fkey(cand);
                    if (!(kc > klo && kc < khi)) cand = funkey(klo + (khi - klo) / 2u);
                }
                unsigned c = 0;
                for (unsigned i2 = t; i2 < mm0; i2 += TPB)
                    c += (sub[i2] < cand) ? 1u : 0u;
                #pragma unroll
                for (int o = 16; o; o >>= 1) c += __shfl_down_sync(0xffffffffu, c, o);
                if (ln == 0) s_wcnt[w] = c;
                __syncthreads();
                if (t == 0)
                    s_tot = (s_wcnt[0] + s_wcnt[1]) + (s_wcnt[2] + s_wcnt[3]);
                __syncthreads();
                const unsigned cg = cL0 + s_tot;
                if (cg <= k0) { lo2 = cand; cLg = cg; }
                else          { hi2 = cand; cHg = cg; }
            }

            /* ---- phase 3: exact select on tiny bracket ---- */
            for (unsigned i2 = t; i2 < mm0; i2 += TPB) {
                float x = sub[i2];
                if (x >= lo2 && x < hi2) {
                    unsigned cl = 0, ce = 0;
                    for (unsigned jj = 0; jj < mm0; ++jj) {
                        float y = sub[jj];
                        cl += (y < x) ? 1u : 0u;
                        ce += (y == x) ? 1u : 0u;
                    }
                    const unsigned glo = cL0 + cl;
                    if (glo <= k0 && k0 < glo + ce)           g_qv[2 * qb + 0] = x;
                    if (glo <= k0 + 1u && k0 + 1u < glo + ce) g_qv[2 * qb + 1] = x;
                }
            }
            /* successor outside bracket: min element >= hi2 (gmem re-scan) */
            if (k0 + 1u >= cHg) {
                float mn = CUDART_INF_F;
                #pragma unroll 4
                for (int e = 0; e < V4PT; ++e) {
                    float4 q = gv4[t + e * TPB];
                    if (q.x >= hi2) mn = fminf(mn, q.x);
                    if (q.y >= hi2) mn = fminf(mn, q.y);
                    if (q.z >= hi2) mn = fminf(mn, q.z);
                    if (q.w >= hi2) mn = fminf(mn, q.w);
                }
                #pragma unroll
                for (int o = 16; o; o >>= 1)
                    mn = fminf(mn, __shfl_down_sync(0xffffffffu, mn, o));
                if (ln == 0) s_fred[w] = mn;
                __syncthreads();
                if (t == 0) {
                    float r = fminf(fminf(s_fred[0], s_fred[1]),
                                    fminf(s_fred[2], s_fred[3]));
                    g_qv[2 * qb + 1] = r;
                }
            }
        }

    } else {
        /* ============ std sums (fp64, deterministic) ============ */
        __shared__ double sds[NWARPS], sdq[NWARPS];
        const float4* gv4 = (const float4*)g;
        double s = 0.0, s2 = 0.0;
        #pragma unroll 4
        for (int e = 0; e < V4PT; ++e) {
            float4 q = gv4[t + e * TPB];
            double x0 = (double)q.x, x1 = (double)q.y;
            double x2 = (double)q.z, x3 = (double)q.w;
            s  += (x0 + x1) + (x2 + x3);
            s2 += (x0 * x0 + x1 * x1) + (x2 * x2 + x3 * x3);
        }
        #pragma unroll
        for (int o = 16; o; o >>= 1) {
            s  += __shfl_down_sync(0xffffffffu, s,  o);
            s2 += __shfl_down_sync(0xffffffffu, s2, o);
        }
        if (ln == 0) { sds[w] = s; sdq[w] = s2; }
        __syncthreads();
        if (t == 0) {
            g_sum_d   = (sds[0] + sds[1]) + (sds[2] + sds[3]);
            g_sumsq_d = (sdq[0] + sdq[1]) + (sdq[2] + sdq[3]);
        }
    }

    /* ============ fused epilogue: last block combines ============ */
    __threadfence();
    __syncthreads();
    if (t == 0) {
        unsigned old = atomicAdd(&g_done, 1u);
        s_last = (old == (unsigned)(GRID - 1)) ? 1 : 0;
    }
    __syncthreads();
    if (s_last) {
        __threadfence();
        if (t < 32) {
            double s = 0.0;
            for (int i2 = t; i2 < NUNITS; i2 += 32) s += g_pair_partial[i2];
            #pragma unroll
            for (int o = 16; o; o >>= 1) s += __shfl_down_sync(0xffffffffu, s, o);
            if (t == 0) {
                double punish = 0.8 - 0.8 * s / NPAIRS_D;
                double var = (g_sumsq_d - g_sum_d * g_sum_d / (double)NTOT)
                             / (double)(NTOT - 1);
                double sd = sqrt(var);
                float q1 = 0.25f * g_qv[0] + 0.75f * g_qv[1];
                float q3 = 0.75f * g_qv[2] + 0.25f * g_qv[3];
                double dstd = sd - RAND_STD;
                double diqr = (double)(q3 - q1) - IQR_RAND;
                out[0] = (float)(punish + dstd * dstd + diqr * diqr);
                g_done = 0;
            }
        }
    }
}

extern "C" void kernel_launch(void* const* d_in, const int* in_sizes, int n_in,
                              void* d_out, int out_size) {
    (void)in_sizes; (void)n_in; (void)out_size;
    const float* g = (const float*)d_in[0];
    float* out = (float*)d_out;
    dp_fused_kernel<<<GRID, TPB, SMEM_BYTES>>>(g, out);
}

// round 7
// speedup vs baseline: 1.0006x; 1.0006x over previous
#include <cuda_runtime.h>
#include <math_constants.h>
#include <stdint.h>

#define NTOT     18432
#define TPB      512
#define TILE     512
#define NSTRIP   12
#define NDIAG    12
#define NUNITS   144                 /* 12 diag + 66*2 offdiag halves */
#define GRID     147
#define EPT      36                  /* NTOT / TPB */
#define NWARPS   16
#define GMAX     2048
#define SELMAX   48
#define SMEM_BYTES 8192              /* float4 tile 512*16 = 8192 | gather 2048 f32 */

static const double NPAIRS_D = 18871296.0;
static const double RAND_STD = 1.75;
static const double IQR_RAND = 2.45;

__device__ double   g_pair_partial[NUNITS];
__device__ double   g_sum_d, g_sumsq_d;
__device__ float    g_qv[4];
__device__ unsigned g_done = 0;

__device__ __forceinline__ float sqrt_approx(float x) {
    float r; asm("sqrt.approx.f32 %0, %1;" : "=f"(r) : "f"(x)); return r;
}
__device__ __forceinline__ float fma_sat(float a, float b, float c) {
    float r; asm("fma.rn.sat.f32 %0, %1, %2, %3;" : "=f"(r) : "f"(a), "f"(b), "f"(c));
    return r;
}
__device__ __forceinline__ unsigned fkey(float f) {
    unsigned u = __float_as_uint(f);
    return (u & 0x80000000u) ? ~u : (u | 0x80000000u);
}
__device__ __forceinline__ float funkey(unsigned u) {
    unsigned bits = (u & 0x80000000u) ? (u & 0x7fffffffu) : ~u;
    return __uint_as_float(bits);
}

__global__ void __launch_bounds__(TPB)
dp_fused_kernel(const float* __restrict__ g, float* __restrict__ out) {
    extern __shared__ unsigned char smem_raw[];
    const int bid = blockIdx.x;
    const int t   = threadIdx.x;
    const int w   = t >> 5;
    const int ln  = t & 31;

    __shared__ unsigned s_wcnt[NWARPS];
    __shared__ unsigned s_tot, s_gcnt;
    __shared__ float    s_fred[NWARPS];
    __shared__ float    s_q[2];
    __shared__ int      s_last;

    if (bid < NUNITS) {
        /* ================= pairwise unit: sum of sqrt(sat(sq/0.64)) ========= */
        int a, b, h;
        if (bid < NDIAG) { a = b = bid; h = -1; }
        else {
            int o = bid - NDIAG;
            int tt = o >> 1; h = o & 1;
            a = 0; int rem = tt;
            while (rem >= NSTRIP - 1 - a) { rem -= NSTRIP - 1 - a; ++a; }
            b = a + 1 + rem;
        }

        float4* tj = (float4*)smem_raw;
        {
            const int j = b * TILE + t;
            float xj = g[3 * j + 0], yj = g[3 * j + 1], zj = g[3 * j + 2];
            float rj = fmaf(zj, zj, fmaf(yj, yj, xj * xj));
            tj[t] = make_float4(xj, yj, zj, 1.5625f * rj);
        }
        __syncthreads();

        float xi, yi, zi;
        if (a == b) {
            float4 me = tj[t];
            xi = me.x; yi = me.y; zi = me.z;
        } else {
            const int i = a * TILE + t;
            xi = g[3 * i + 0]; yi = g[3 * i + 1]; zi = g[3 * i + 2];
        }
        const float R = 1.5625f * fmaf(zi, zi, fmaf(yi, yi, xi * xi));
        const float A = -3.125f * xi, B = -3.125f * yi, C = -3.125f * zi;

        float acc0 = 0.f, acc1 = 0.f;

        if (h < 0) {
            /* diag: wrap mapping d = 1..255 all threads, d = 256 for t < 256 */
            #pragma unroll 4
            for (int d = 1; d <= 255; ++d) {
                float4 o = tj[(t + d) & (TILE - 1)];
                float u = fma_sat(C, o.z, fmaf(B, o.y, fmaf(A, o.x, R + o.w)));
                if (d & 1) acc0 += sqrt_approx(u); else acc1 += sqrt_approx(u);
            }
            if (t < TILE / 2) {
                float4 o = tj[(t + 256) & (TILE - 1)];
                float u = fma_sat(C, o.z, fmaf(B, o.y, fmaf(A, o.x, R + o.w)));
                acc0 += sqrt_approx(u);
            }
        } else {
            const int j0 = h * (TILE / 2);
            const int j1 = j0 + TILE / 2;
            #pragma unroll 8
            for (int jj = j0; jj < j1; jj += 2) {
                {
                    float4 o = tj[jj];
                    float u = fma_sat(C, o.z, fmaf(B, o.y, fmaf(A, o.x, R + o.w)));
                    acc0 += sqrt_approx(u);
                }
                {
                    float4 o = tj[jj + 1];
                    float u = fma_sat(C, o.z, fmaf(B, o.y, fmaf(A, o.x, R + o.w)));
                    acc1 += sqrt_approx(u);
                }
            }
        }

        float tot = acc0 + acc1;
        #pragma unroll
        for (int o = 16; o; o >>= 1)
            tot += __shfl_down_sync(0xffffffffu, tot, o);
        if (ln == 0) s_fred[w] = tot;
        __syncthreads();
        if (t == 0) {
            float r = 0.f;
            #pragma unroll
            for (int i2 = 0; i2 < NWARPS; ++i2) r += s_fred[i2];
            g_pair_partial[bid] = (double)r;
        }

    } else if (bid < NUNITS + 2) {
        /* ========= exact quantile pair (ranks k0, k0+1), 3-phase ========= */
        const int qb = bid - NUNITS;
        const unsigned k0 = qb ? 13823u : 4607u;
        const float gA = qb ? 0.6245f : -0.7245f;
        const float gB = qb ? 0.7245f : -0.6245f;

        float v[EPT];
        #pragma unroll
        for (int e = 0; e < EPT; ++e) v[e] = g[t + e * TPB];

        float lo = -CUDART_INF_F, hi = CUDART_INF_F;
        unsigned cL = 0, cH = NTOT;
        bool allEq = false;

        /* ---- phase 1: register passes until bracket <= GMAX ---- */
        for (int it = 0; it < 48; ++it) {
            if (cH - cL <= (unsigned)GMAX) break;
            const unsigned klo = fkey(lo), khi = fkey(hi);
            if (khi - klo <= 1u) { allEq = true; break; }
            float cand;
            if (it == 0)      cand = gA;
            else if (it == 1) cand = gB;
            else if (it < 8) {
                double frac = ((double)k0 + 0.5 - (double)cL) / (double)(cH - cL);
                cand = (float)((double)lo + frac * ((double)hi - (double)lo));
            } else cand = funkey(klo + (khi - klo) / 2u);
            {
                unsigned kc = fkey(cand);
                if (!(kc > klo && kc < khi)) cand = funkey(klo + (khi - klo) / 2u);
            }
            unsigned c = 0;
            #pragma unroll
            for (int e = 0; e < EPT; ++e) c += (v[e] < cand) ? 1u : 0u;
            #pragma unroll
            for (int o = 16; o; o >>= 1) c += __shfl_down_sync(0xffffffffu, c, o);
            if (ln == 0) s_wcnt[w] = c;
            __syncthreads();
            if (t == 0) {
                unsigned totc = 0;
                #pragma unroll
                for (int i2 = 0; i2 < NWARPS; ++i2) totc += s_wcnt[i2];
                s_tot = totc;
            }
            __syncthreads();
            const unsigned ctot = s_tot;
            if (ctot <= k0) { lo = cand; cL = ctot; }
            else            { hi = cand; cH = ctot; }
        }

        if (allEq) {
            if (t == 0) { s_q[0] = lo; s_q[1] = lo; }
            __syncthreads();
        } else {
            /* ---- gather bracket [lo,hi) into smem ---- */
            float* sub = (float*)smem_raw;
            if (t == 0) s_gcnt = 0;
            __syncthreads();
            #pragma unroll
            for (int e = 0; e < EPT; ++e) {
                float x = v[e];
                if (x >= lo && x < hi) {
                    unsigned p = atomicAdd(&s_gcnt, 1u);
                    if (p < (unsigned)GMAX) sub[p] = x;
                }
            }
            __syncthreads();
            const unsigned mm0 = s_gcnt;
            const unsigned cL0 = cL;

            /* ---- phase 2: smem count passes until bracket <= SELMAX ---- */
            unsigned cLg = cL, cHg = cH;
            float lo2 = lo, hi2 = hi;
            for (int it = 0; it < 64; ++it) {
                if (cHg - cLg <= (unsigned)SELMAX) break;
                const unsigned klo = fkey(lo2), khi = fkey(hi2);
                if (khi - klo <= 1u) break;
                float cand;
                if (it < 10) {
                    double frac = ((double)k0 + 0.5 - (double)cLg) / (double)(cHg - cLg);
                    cand = (float)((double)lo2 + frac * ((double)hi2 - (double)lo2));
                } else cand = funkey(klo + (khi - klo) / 2u);
                {
                    unsigned kc = fkey(cand);
                    if (!(kc > klo && kc < khi)) cand = funkey(klo + (khi - klo) / 2u);
                }
                unsigned c = 0;
                for (unsigned i2 = t; i2 < mm0; i2 += TPB)
                    c += (sub[i2] < cand) ? 1u : 0u;
                #pragma unroll
                for (int o = 16; o; o >>= 1) c += __shfl_down_sync(0xffffffffu, c, o);
                if (ln == 0) s_wcnt[w] = c;
                __syncthreads();
                if (t == 0) {
                    unsigned totc = 0;
                    #pragma unroll
                    for (int i2 = 0; i2 < NWARPS; ++i2) totc += s_wcnt[i2];
                    s_tot = totc;
                }
                __syncthreads();
                const unsigned cg = cL0 + s_tot;
                if (cg <= k0) { lo2 = cand; cLg = cg; }
                else          { hi2 = cand; cHg = cg; }
            }

            /* ---- phase 3: exact select on tiny bracket (results -> smem) ---- */
            for (unsigned i2 = t; i2 < mm0; i2 += TPB) {
                float x = sub[i2];
                if (x >= lo2 && x < hi2) {
                    unsigned cl = 0, ce = 0;
                    for (unsigned jj = 0; jj < mm0; ++jj) {
                        float y = sub[jj];
                        cl += (y < x) ? 1u : 0u;
                        ce += (y == x) ? 1u : 0u;
                    }
                    const unsigned glo = cL0 + cl;
                    if (glo <= k0 && k0 < glo + ce)           s_q[0] = x;
                    if (glo <= k0 + 1u && k0 + 1u < glo + ce) s_q[1] = x;
                }
            }
            /* successor outside bracket: v[k0+1] = min element >= hi2 */
            if (k0 + 1u >= cHg) {
                float mn = CUDART_INF_F;
                #pragma unroll
                for (int e = 0; e < EPT; ++e)
                    if (v[e] >= hi2) mn = fminf(mn, v[e]);
                #pragma unroll
                for (int o = 16; o; o >>= 1)
                    mn = fminf(mn, __shfl_down_sync(0xffffffffu, mn, o));
                if (ln == 0) s_fred[w] = mn;
                __syncthreads();
                if (t == 0) {
                    float r = s_fred[0];
                    #pragma unroll
                    for (int i2 = 1; i2 < NWARPS; ++i2) r = fminf(r, s_fred[i2]);
                    s_q[1] = r;
                }
            }
            __syncthreads();
        }
        if (t == 0) {
            g_qv[2 * qb + 0] = s_q[0];
            g_qv[2 * qb + 1] = s_q[1];
        }

    } else {
        /* ============ std sums (fp64, deterministic) ============ */
        __shared__ double sds[NWARPS], sdq[NWARPS];
        double s = 0.0, s2 = 0.0;
        #pragma unroll
        for (int e = 0; e < EPT; ++e) {
            double x = (double)g[t + e * TPB];
            s += x; s2 += x * x;
        }
        #pragma unroll
        for (int o = 16; o; o >>= 1) {
            s  += __shfl_down_sync(0xffffffffu, s,  o);
            s2 += __shfl_down_sync(0xffffffffu, s2, o);
        }
        if (ln == 0) { sds[w] = s; sdq[w] = s2; }
        __syncthreads();
        if (t == 0) {
            double aa = 0.0, bb = 0.0;
            #pragma unroll
            for (int i2 = 0; i2 < NWARPS; ++i2) { aa += sds[i2]; bb += sdq[i2]; }
            g_sum_d = aa; g_sumsq_d = bb;
        }
    }

    /* ====== fused epilogue: thread-0-only release; last block combines ====== */
    __syncthreads();
    if (t == 0) {
        __threadfence();                      /* order this block's global sts */
        unsigned old = atomicAdd(&g_done, 1u);
        s_last = (old == (unsigned)(GRID - 1)) ? 1 : 0;
    }
    __syncthreads();
    if (s_last) {
        if (t < 32) {
            __threadfence();                  /* acquire */
            double s = 0.0;
            for (int i2 = t; i2 < NUNITS; i2 += 32) s += g_pair_partial[i2];
            #pragma unroll
            for (int o = 16; o; o >>= 1) s += __shfl_down_sync(0xffffffffu, s, o);
            if (t == 0) {
                double punish = 0.8 - 0.8 * s / NPAIRS_D;
                double var = (g_sumsq_d - g_sum_d * g_sum_d / (double)NTOT)
                             / (double)(NTOT - 1);
                double sd = sqrt(var);
                float q1 = 0.25f * g_qv[0] + 0.75f * g_qv[1];
                float q3 = 0.75f * g_qv[2] + 0.25f * g_qv[3];
                double dstd = sd - RAND_STD;
                double diqr = (double)(q3 - q1) - IQR_RAND;
                out[0] = (float)(punish + dstd * dstd + diqr * diqr);
                g_done = 0;                   /* reset for next replay */
            }
        }
    }
}

extern "C" void kernel_launch(void* const* d_in, const int* in_sizes, int n_in,
                              void* d_out, int out_size) {
    (void)in_sizes; (void)n_in; (void)out_size;
    const float* g = (const float*)d_in[0];
    float* out = (float*)d_out;
    dp_fused_kernel<<<GRID, TPB, SMEM_BYTES>>>(g, out);
}

// round 8
// speedup vs baseline: 1.2589x; 1.2581x over previous
#include <cuda_runtime.h>
#include <math_constants.h>
#include <stdint.h>

#define NTOT     18432
#define TPB      256
#define TILE     256
#define NSTRIP   24
#define NDIAG    24
#define NUNITS   576                 /* 24 diag + 276*2 offdiag halves */
#define GRID     579                 /* 2 quantile + 1 std + 576 pairwise */
#define NWARPS   8
#define V4PT     18                  /* NTOT/4/TPB */
#define GMAX     1024
#define SELMAX   48
#define SMEM_BYTES 4096              /* float4 tile 256*16 | gather 1024 f32 */

static const double NPAIRS_D = 18871296.0;
static const double RAND_STD = 1.75;
static const double IQR_RAND = 2.45;

__device__ double   g_pair_partial[NUNITS];
__device__ double   g_sum_d, g_sumsq_d;
__device__ float    g_qv[4];
__device__ unsigned g_c1[32 * 64];   /* level-1 counters, 256B stride */
__device__ unsigned g_c2 = 0;

__device__ __forceinline__ float sqrt_approx(float x) {
    float r; asm("sqrt.approx.f32 %0, %1;" : "=f"(r) : "f"(x)); return r;
}
__device__ __forceinline__ float fma_sat(float a, float b, float c) {
    float r; asm("fma.rn.sat.f32 %0, %1, %2, %3;" : "=f"(r) : "f"(a), "f"(b), "f"(c));
    return r;
}
__device__ __forceinline__ unsigned fkey(float f) {
    unsigned u = __float_as_uint(f);
    return (u & 0x80000000u) ? ~u : (u | 0x80000000u);
}
__device__ __forceinline__ float funkey(unsigned u) {
    unsigned bits = (u & 0x80000000u) ? (u & 0x7fffffffu) : ~u;
    return __uint_as_float(bits);
}

__global__ void __launch_bounds__(TPB, 4)
dp_fused_kernel(const float* __restrict__ g, float* __restrict__ out) {
    extern __shared__ unsigned char smem_raw[];
    const int bid = blockIdx.x;
    const int t   = threadIdx.x;
    const int w   = t >> 5;
    const int ln  = t & 31;

    __shared__ unsigned s_wcnt[NWARPS];
    __shared__ unsigned s_tot, s_gcnt;
    __shared__ float    s_fred[NWARPS];
    __shared__ float    s_q[2];
    __shared__ int      s_last;

    if (bid >= 3) {
        /* ========== pairwise unit: sum sqrt(sat(sq/0.64)), ~32.7K pairs ===== */
        const int pid = bid - 3;
        int a, b, h;
        if (pid < NDIAG) { a = b = pid; h = -1; }
        else {
            int o = pid - NDIAG;
            int tt = o >> 1; h = o & 1;
            a = 0; int rem = tt;
            while (rem >= NSTRIP - 1 - a) { rem -= NSTRIP - 1 - a; ++a; }
            b = a + 1 + rem;
        }

        float4* tj = (float4*)smem_raw;
        {
            const int j = b * TILE + t;
            float xj = g[3 * j + 0], yj = g[3 * j + 1], zj = g[3 * j + 2];
            float rj = fmaf(zj, zj, fmaf(yj, yj, xj * xj));
            tj[t] = make_float4(xj, yj, zj, 1.5625f * rj);
        }
        __syncthreads();

        float xi, yi, zi;
        if (h < 0) {
            float4 me = tj[t];
            xi = me.x; yi = me.y; zi = me.z;
        } else {
            const int i = a * TILE + t;
            xi = g[3 * i + 0]; yi = g[3 * i + 1]; zi = g[3 * i + 2];
        }
        const float R = 1.5625f * fmaf(zi, zi, fmaf(yi, yi, xi * xi));
        const float A = -3.125f * xi, B = -3.125f * yi, C = -3.125f * zi;

        float acc0 = 0.f, acc1 = 0.f;

        if (h < 0) {
            /* diag: wrap d = 1..127 all threads; d = 128 for t < 128 */
            #pragma unroll 8
            for (int d = 1; d <= 127; ++d) {
                float4 o = tj[(t + d) & (TILE - 1)];
                float u = fma_sat(C, o.z, fmaf(B, o.y, fmaf(A, o.x, R + o.w)));
                if (d & 1) acc0 += sqrt_approx(u); else acc1 += sqrt_approx(u);
            }
            if (t < TILE / 2) {
                float4 o = tj[(t + 128) & (TILE - 1)];
                float u = fma_sat(C, o.z, fmaf(B, o.y, fmaf(A, o.x, R + o.w)));
                acc0 += sqrt_approx(u);
            }
        } else {
            const int j0 = h * (TILE / 2);
            const int j1 = j0 + TILE / 2;
            #pragma unroll 8
            for (int jj = j0; jj < j1; jj += 2) {
                {
                    float4 o = tj[jj];
                    float u = fma_sat(C, o.z, fmaf(B, o.y, fmaf(A, o.x, R + o.w)));
                    acc0 += sqrt_approx(u);
                }
                {
                    float4 o = tj[jj + 1];
                    float u = fma_sat(C, o.z, fmaf(B, o.y, fmaf(A, o.x, R + o.w)));
                    acc1 += sqrt_approx(u);
                }
            }
        }

        float tot = acc0 + acc1;
        #pragma unroll
        for (int o = 16; o; o >>= 1)
            tot += __shfl_down_sync(0xffffffffu, tot, o);
        if (ln == 0) s_fred[w] = tot;
        __syncthreads();
        if (t == 0) {
            float r = 0.f;
            #pragma unroll
            for (int i2 = 0; i2 < NWARPS; ++i2) r += s_fred[i2];
            g_pair_partial[pid] = (double)r;
        }

    } else if (bid < 2) {
        /* ========= exact quantile pair (ranks k0, k0+1), 3-phase ========= */
        const int qb = bid;
        const unsigned k0 = qb ? 13823u : 4607u;
        const float gA = qb ? 0.6245f : -0.7245f;
        const float gB = qb ? 0.7245f : -0.6245f;
        const float4* gv4 = (const float4*)g;

        float lo = -CUDART_INF_F, hi = CUDART_INF_F;
        unsigned cL = 0, cH = NTOT;
        bool allEq = false;

        /* ---- phase 1: gmem passes (L1-resident) until bracket <= GMAX ---- */
        for (int it = 0; it < 48; ++it) {
            if (cH - cL <= (unsigned)GMAX) break;
            const unsigned klo = fkey(lo), khi = fkey(hi);
            if (khi - klo <= 1u) { allEq = true; break; }
            float cand;
            if (it == 0)      cand = gA;
            else if (it == 1) cand = gB;
            else if (it < 8) {
                double frac = ((double)k0 + 0.5 - (double)cL) / (double)(cH - cL);
                cand = (float)((double)lo + frac * ((double)hi - (double)lo));
            } else cand = funkey(klo + (khi - klo) / 2u);
            {
                unsigned kc = fkey(cand);
                if (!(kc > klo && kc < khi)) cand = funkey(klo + (khi - klo) / 2u);
            }
            unsigned c = 0;
            #pragma unroll 3
            for (int e = 0; e < V4PT; ++e) {
                float4 q = gv4[t + e * TPB];
                c += (q.x < cand) ? 1u : 0u;
                c += (q.y < cand) ? 1u : 0u;
                c += (q.z < cand) ? 1u : 0u;
                c += (q.w < cand) ? 1u : 0u;
            }
            #pragma unroll
            for (int o = 16; o; o >>= 1) c += __shfl_down_sync(0xffffffffu, c, o);
            if (ln == 0) s_wcnt[w] = c;
            __syncthreads();
            if (t == 0) {
                unsigned totc = 0;
                #pragma unroll
                for (int i2 = 0; i2 < NWARPS; ++i2) totc += s_wcnt[i2];
                s_tot = totc;
            }
            __syncthreads();
            const unsigned ctot = s_tot;
            if (ctot <= k0) { lo = cand; cL = ctot; }
            else            { hi = cand; cH = ctot; }
        }

        if (allEq) {
            if (t == 0) { s_q[0] = lo; s_q[1] = lo; }
            __syncthreads();
        } else {
            /* ---- gather bracket [lo,hi) into smem ---- */
            float* sub = (float*)smem_raw;
            if (t == 0) s_gcnt = 0;
            __syncthreads();
            #pragma unroll 3
            for (int e = 0; e < V4PT; ++e) {
                float4 q = gv4[t + e * TPB];
                float qq[4] = {q.x, q.y, q.z, q.w};
                #pragma unroll
                for (int c4 = 0; c4 < 4; ++c4) {
                    float x = qq[c4];
                    if (x >= lo && x < hi) {
                        unsigned p = atomicAdd(&s_gcnt, 1u);
                        if (p < (unsigned)GMAX) sub[p] = x;
                    }
                }
            }
            __syncthreads();
            const unsigned mm0 = s_gcnt;
            const unsigned cL0 = cL;

            /* ---- phase 2: smem count passes until bracket <= SELMAX ---- */
            unsigned cLg = cL, cHg = cH;
            float lo2 = lo, hi2 = hi;
            for (int it = 0; it < 64; ++it) {
                if (cHg - cLg <= (unsigned)SELMAX) break;
                const unsigned klo = fkey(lo2), khi = fkey(hi2);
                if (khi - klo <= 1u) break;
                float cand;
                if (it < 10) {
                    double frac = ((double)k0 + 0.5 - (double)cLg) / (double)(cHg - cLg);
                    cand = (float)((double)lo2 + frac * ((double)hi2 - (double)lo2));
                } else cand = funkey(klo + (khi - klo) / 2u);
                {
                    unsigned kc = fkey(cand);
                    if (!(kc > klo && kc < khi)) cand = funkey(klo + (khi - klo) / 2u);
                }
                unsigned c = 0;
                for (unsigned i2 = t; i2 < mm0; i2 += TPB)
                    c += (sub[i2] < cand) ? 1u : 0u;
                #pragma unroll
                for (int o = 16; o; o >>= 1) c += __shfl_down_sync(0xffffffffu, c, o);
                if (ln == 0) s_wcnt[w] = c;
                __syncthreads();
                if (t == 0) {
                    unsigned totc = 0;
                    #pragma unroll
                    for (int i2 = 0; i2 < NWARPS; ++i2) totc += s_wcnt[i2];
                    s_tot = totc;
                }
                __syncthreads();
                const unsigned cg = cL0 + s_tot;
                if (cg <= k0) { lo2 = cand; cLg = cg; }
                else          { hi2 = cand; cHg = cg; }
            }

            /* ---- phase 3: exact select on tiny bracket (results -> smem) ---- */
            for (unsigned i2 = t; i2 < mm0; i2 += TPB) {
                float x = sub[i2];
                if (x >= lo2 && x < hi2) {
                    unsigned cl = 0, ce = 0;
                    for (unsigned jj = 0; jj < mm0; ++jj) {
                        float y = sub[jj];
                        cl += (y < x) ? 1u : 0u;
                        ce += (y == x) ? 1u : 0u;
                    }
                    const unsigned glo = cL0 + cl;
                    if (glo <= k0 && k0 < glo + ce)           s_q[0] = x;
                    if (glo <= k0 + 1u && k0 + 1u < glo + ce) s_q[1] = x;
                }
            }
            /* successor outside bracket: min element >= hi2 (gmem re-scan) */
            if (k0 + 1u >= cHg) {
                float mn = CUDART_INF_F;
                #pragma unroll 3
                for (int e = 0; e < V4PT; ++e) {
                    float4 q = gv4[t + e * TPB];
                    if (q.x >= hi2) mn = fminf(mn, q.x);
                    if (q.y >= hi2) mn = fminf(mn, q.y);
                    if (q.z >= hi2) mn = fminf(mn, q.z);
                    if (q.w >= hi2) mn = fminf(mn, q.w);
                }
                #pragma unroll
                for (int o = 16; o; o >>= 1)
                    mn = fminf(mn, __shfl_down_sync(0xffffffffu, mn, o));
                if (ln == 0) s_fred[w] = mn;
                __syncthreads();
                if (t == 0) {
                    float r = s_fred[0];
                    #pragma unroll
                    for (int i2 = 1; i2 < NWARPS; ++i2) r = fminf(r, s_fred[i2]);
                    s_q[1] = r;
                }
            }
            __syncthreads();
        }
        if (t == 0) {
            g_qv[2 * qb + 0] = s_q[0];
            g_qv[2 * qb + 1] = s_q[1];
        }

    } else {
        /* ============ std sums (fp64, deterministic) ============ */
        __shared__ double sds[NWARPS], sdq[NWARPS];
        const float4* gv4 = (const float4*)g;
        double s = 0.0, s2 = 0.0;
        #pragma unroll 3
        for (int e = 0; e < V4PT; ++e) {
            float4 q = gv4[t + e * TPB];
            double x0 = (double)q.x, x1 = (double)q.y;
            double x2 = (double)q.z, x3 = (double)q.w;
            s  += (x0 + x1) + (x2 + x3);
            s2 += (x0 * x0 + x1 * x1) + (x2 * x2 + x3 * x3);
        }
        #pragma unroll
        for (int o = 16; o; o >>= 1) {
            s  += __shfl_down_sync(0xffffffffu, s,  o);
            s2 += __shfl_down_sync(0xffffffffu, s2, o);
        }
        if (ln == 0) { sds[w] = s; sdq[w] = s2; }
        __syncthreads();
        if (t == 0) {
            double aa = 0.0, bb = 0.0;
            #pragma unroll
            for (int i2 = 0; i2 < NWARPS; ++i2) { aa += sds[i2]; bb += sdq[i2]; }
            g_sum_d = aa; g_sumsq_d = bb;
        }
    }

    /* ====== two-level completion barrier; last block combines ====== */
    __syncthreads();
    if (t == 0) {
        __threadfence();                       /* release this block's stores */
        const int r = bid & 31;
        const unsigned quota = 18u + ((r < (GRID & 31)) ? 1u : 0u);
        int last = 0;
        unsigned old = atomicAdd(&g_c1[r * 64], 1u);
        if (old == quota - 1u) {
            unsigned old2 = atomicAdd(&g_c2, 1u);
            last = (old2 == 31u);
        }
        s_last = last;
    }
    __syncthreads();
    if (s_last) {
        if (t < 32) {
            __threadfence();                   /* acquire */
            double s = 0.0;
            for (int i2 = t; i2 < NUNITS; i2 += 32) s += g_pair_partial[i2];
            #pragma unroll
            for (int o = 16; o; o >>= 1) s += __shfl_down_sync(0xffffffffu, s, o);
            /* reset counters for next graph replay */
            g_c1[t * 64] = 0u;
            if (t == 0) {
                g_c2 = 0u;
                double punish = 0.8 - 0.8 * s / NPAIRS_D;
                double var = (g_sumsq_d - g_sum_d * g_sum_d / (double)NTOT)
                             / (double)(NTOT - 1);
                double sd = sqrt(var);
                float q1 = 0.25f * g_qv[0] + 0.75f * g_qv[1];
                float q3 = 0.75f * g_qv[2] + 0.25f * g_qv[3];
                double dstd = sd - RAND_STD;
                double diqr = (double)(q3 - q1) - IQR_RAND;
                out[0] = (float)(punish + dstd * dstd + diqr * diqr);
            }
        }
    }
}

extern "C" void kernel_launch(void* const* d_in, const int* in_sizes, int n_in,
                              void* d_out, int out_size) {
    (void)in_sizes; (void)n_in; (void)out_size;
    const float* g = (const float*)d_in[0];
    float* out = (float*)d_out;
    dp_fused_kernel<<<GRID, TPB, SMEM_BYTES>>>(g, out);
}